// round 6
// baseline (speedup 1.0000x reference)
#include <cuda_runtime.h>
#include <math.h>

#define DD 128
static const int NC = DD * DD * DD;   // cells per layer

// smem: 6 fields x 18 rows (3z x 6y halo) x 128 units x (l0,l1) interleaved
#define ROWS 18
#define ROWF 256                      // floats per row (128 units * 2 layers)
#define FSTRIDE (ROWS * ROWF)         // 4608 floats per field
#define SMEM_FLOATS (6 * FSTRIDE)     // 27648 floats = 110592 B

typedef unsigned long long f2;        // packed f32x2

__device__ __forceinline__ f2 pk(float lo, float hi) {
    f2 r; asm("mov.b64 %0,{%1,%2};" : "=l"(r) : "f"(lo), "f"(hi)); return r;
}
__device__ __forceinline__ void up(f2 v, float& lo, float& hi) {
    asm("mov.b64 {%0,%1},%2;" : "=f"(lo), "=f"(hi) : "l"(v));
}
__device__ __forceinline__ f2 fma2(f2 a, f2 b, f2 c) {
    f2 d; asm("fma.rn.f32x2 %0,%1,%2,%3;" : "=l"(d) : "l"(a), "l"(b), "l"(c)); return d;
}
__device__ __forceinline__ f2 mul2(f2 a, f2 b) {
    f2 d; asm("mul.rn.f32x2 %0,%1,%2;" : "=l"(d) : "l"(a), "l"(b)); return d;
}
__device__ __forceinline__ float rsqrt_fast(float x) {
    float y; asm("rsqrt.approx.f32 %0, %1;" : "=f"(y) : "f"(x)); return y;
}

__device__ __forceinline__ float boundary_force(float p, float v, float mv, float ETAf) {
    float lo = (p > 0.1f && p < 0.15f) ? mv : 0.0f;
    float hi = (p > 12.65f) ? mv : 0.0f;
    float fb = 6.0e6f * lo * (0.15f - p);
    fb -= 6.0e6f * hi * (((p - 12.8f) + 0.1f) + 0.05f);
    fb -= ETAf * v * lo;
    fb -= ETAf * v * hi;
    return fb;
}

struct Consts { f2 NEG1, EPS2, KN2, NKPS2, ETA2; };

// One packed interaction: 1 center cell (duplicated into both lanes of C[0..5])
// vs a (layer0, layer1) neighbor unit W*. No repacking needed — W comes
// straight from an aligned LDS.64 of the layer-interleaved tile.
__device__ __forceinline__ void interact(
    const f2* __restrict__ C,
    f2 WX, f2 WY, f2 WZ, f2 WVX, f2 WVY, f2 WVZ,
    f2& FX, f2& FY, f2& FZ, const Consts& K)
{
    f2 dx2 = fma2(WX, K.NEG1, C[0]);
    f2 dy2 = fma2(WY, K.NEG1, C[1]);
    f2 dz2 = fma2(WZ, K.NEG1, C[2]);
    f2 s2  = fma2(dz2, dz2, K.EPS2);     // +1e-8 floor folded in
    s2 = fma2(dy2, dy2, s2);
    s2 = fma2(dx2, dx2, s2);
    float s0, s1; up(s2, s0, s1);
    float r0 = rsqrt_fast(s0);
    float r1 = rsqrt_fast(s1);
    r0 = (s0 < 0.01f) ? r0 : 0.0f;       // contact gate folded into r
    r1 = (s1 < 0.01f) ? r1 : 0.0f;
    f2 rg = pk(r0, r1);
    f2 dist2 = mul2(s2, rg);             // = sqrt(s2) where gated-in, else 0
    f2 dvx2 = fma2(WVX, K.NEG1, C[3]);
    f2 dvy2 = fma2(WVY, K.NEG1, C[4]);
    f2 dvz2 = fma2(WVZ, K.NEG1, C[5]);
    f2 dot2 = mul2(dvz2, dz2);
    dot2 = fma2(dvy2, dy2, dot2);
    dot2 = fma2(dvx2, dx2, dot2);
    f2 q2 = mul2(dot2, rg);              // dvn/dc (dc clamp automatic: r<=1e4)
    f2 t2 = fma2(K.KN2, dist2, K.NKPS2); // KN*(dist-PS)
    t2 = fma2(K.ETA2, q2, t2);
    f2 coef2 = mul2(t2, rg);             // zero where gated-out
    FX = fma2(coef2, dx2, FX);
    FY = fma2(coef2, dy2, FY);
    FZ = fma2(coef2, dz2, FZ);
}

__global__ void __launch_bounds__(512, 1)
dem_pass(const float* __restrict__ nx0, const float* __restrict__ ny0, const float* __restrict__ nz0,
         const float* __restrict__ nvx0, const float* __restrict__ nvy0, const float* __restrict__ nvz0,
         const float* __restrict__ nx1, const float* __restrict__ ny1, const float* __restrict__ nz1,
         const float* __restrict__ nvx1, const float* __restrict__ nvy1, const float* __restrict__ nvz1,
         const float* __restrict__ cx, const float* __restrict__ cy, const float* __restrict__ cz,
         const float* __restrict__ cvx, const float* __restrict__ cvy, const float* __restrict__ cvz,
         const float* __restrict__ cmask,
         float* __restrict__ ovx, float* __restrict__ ovy, float* __restrict__ ovz,
         float ETAf, float DTPMf, float GPMf)
{
    extern __shared__ float sm[];

    const int lane = threadIdx.x;            // 0..31
    const int wid  = threadIdx.y;            // 0..15
    const int tid  = wid * 32 + lane;        // 0..511
    const int x    = (wid & 3) * 32 + lane;  // 0..127
    const int yl   = wid >> 2;               // 0..3
    const int by4  = blockIdx.x * 4;
    const int y    = by4 + yl;
    const int z    = blockIdx.y;
    const int base = (z * DD + y) * DD + x;

    Consts K;
    K.NEG1  = pk(-1.0f, -1.0f);
    K.EPS2  = pk(1e-8f, 1e-8f);
    K.KN2   = pk(6.0e6f, 6.0e6f);
    K.NKPS2 = pk(-600000.0f, -600000.0f);
    K.ETA2  = pk(ETAf, ETAf);

    // center cell (layer n), duplicated into both packed lanes
    const float mk = cmask[base];
    f2 C[6];
    {
        float v;
        v = cx[base];  C[0] = pk(v, v);
        v = cy[base];  C[1] = pk(v, v);
        v = cz[base];  C[2] = pk(v, v);
        v = cvx[base]; C[3] = pk(v, v);
        v = cvy[base]; C[4] = pk(v, v);
        v = cvz[base]; C[5] = pk(v, v);
    }

    // fill smem: 6 fields x 18 rows x 128 units, layer-interleaved
    {
        const float* NL0[6] = {nx0, ny0, nz0, nvx0, nvy0, nvz0};
        const float* NL1[6] = {nx1, ny1, nz1, nvx1, nvy1, nvz1};
        // 3456 float4-groups total
        for (int g = tid; g < 3456; g += 512) {
            int f = g / 576, rem = g - f * 576;
            int r = rem >> 5, x4 = (rem & 31) * 4;
            int gy = (by4 + (r % 6) - 1 + DD) & 127;
            int gz = (z + (r / 6) - 1 + DD) & 127;
            int gi = (gz * DD + gy) * DD + x4;
            float4 a = *reinterpret_cast<const float4*>(NL0[f] + gi);
            float4 b = *reinterpret_cast<const float4*>(NL1[f] + gi);
            float2* s = reinterpret_cast<float2*>(sm + f * FSTRIDE + r * ROWF + x4 * 2);
            s[0] = make_float2(a.x, b.x);
            s[1] = make_float2(a.y, b.y);
            s[2] = make_float2(a.z, b.z);
            s[3] = make_float2(a.w, b.w);
        }
    }
    __syncthreads();

    // float-index offsets of the three x-columns (wrap via mask; always 8B-aligned)
    const int oxm = ((x + 127) & 127) * 2;
    const int ox0 = x * 2;
    const int oxp = ((x + 1) & 127) * 2;

    f2 FX = 0, FY = 0, FZ = 0;

#pragma unroll
    for (int dz = 0; dz < 3; ++dz) {
#pragma unroll
        for (int dy = 0; dy < 3; ++dy) {
            const int rbase = (dz * 6 + yl + dy) * ROWF;
            f2 Wm[6], W0[6], Wp[6];
#pragma unroll
            for (int f = 0; f < 6; ++f) {
                const float* rp = sm + f * FSTRIDE + rbase;
                Wm[f] = *reinterpret_cast<const f2*>(rp + oxm);
                W0[f] = *reinterpret_cast<const f2*>(rp + ox0);
                Wp[f] = *reinterpret_cast<const f2*>(rp + oxp);
            }
            interact(C, Wm[0], Wm[1], Wm[2], Wm[3], Wm[4], Wm[5], FX, FY, FZ, K);
            interact(C, W0[0], W0[1], W0[2], W0[3], W0[4], W0[5], FX, FY, FZ, K);
            interact(C, Wp[0], Wp[1], Wp[2], Wp[3], Wp[4], Wp[5], FX, FY, FZ, K);
        }
    }

    // reduce packed (layer0 + layer1) contributions
    float lo, hi;
    up(FX, lo, hi); const float fxa = lo + hi;
    up(FY, lo, hi); const float fya = lo + hi;
    up(FZ, lo, hi); const float fza = lo + hi;

    // recover center scalars from duplicated packs
    float xn, yn, zn, vxn, vyn, vzn, d_;
    up(C[0], xn, d_); up(C[1], yn, d_); up(C[2], zn, d_);
    up(C[3], vxn, d_); up(C[4], vyn, d_); up(C[5], vzn, d_);

    const float fxb = boundary_force(xn, vxn, mk, ETAf);
    const float fyb = boundary_force(yn, vyn, mk, ETAf);
    const float fzb = boundary_force(zn, vzn, mk, ETAf);
    const float sc = DTPMf * mk;
    ovx[base] = vxn + sc * (fxb - fxa);
    ovy[base] = vyn + sc * (fyb - fya);
    ovz[base] = vzn + sc * ((GPMf - fza) + fzb);
}

extern "C" void kernel_launch(void* const* d_in, const int* in_sizes, int n_in,
                              void* d_out, int out_size)
{
    const float* x  = (const float*)d_in[0];
    const float* y  = (const float*)d_in[1];
    const float* z  = (const float*)d_in[2];
    const float* vx = (const float*)d_in[3];
    const float* vy = (const float*)d_in[4];
    const float* vz = (const float*)d_in[5];
    const float* mask = (const float*)d_in[6];
    float* out = (float*)d_out;
    const int N = NC;

    const double PI = 3.141592653589793;
    const double ALPHA = 0.6931471805599453 / PI;          // -log(0.5)/pi
    const double GAMMA = ALPHA / sqrt(ALPHA * ALPHA + 1.0);
    const double PM = 4.0 / 3.0 * 3.1415 * (0.1 * 0.1 * 0.1) * 2700.0;
    const double ETA = 2.0 * GAMMA * sqrt(6.0e6 * PM);
    const float ETAf  = (float)ETA;
    const float DTPMf = (float)(1e-4 / PM);
    const float GPMf  = (float)(-9.8 * PM);

    cudaFuncSetAttribute(dem_pass, cudaFuncAttributeMaxDynamicSharedMemorySize,
                         SMEM_FLOATS * (int)sizeof(float));

    dim3 grid(32, 128);       // 128/4 y-tiles, 128 z-planes
    dim3 block(32, 16);       // 512 threads, 1 cell each
    size_t shmem = SMEM_FLOATS * sizeof(float);

    // pass n = 0: neighbors use original velocities of both layers; center = layer 0
    dem_pass<<<grid, block, shmem>>>(
        x, y, z, vx, vy, vz,
        x + N, y + N, z + N, vx + N, vy + N, vz + N,
        x, y, z, vx, vy, vz,
        mask,
        out + 0 * N, out + 2 * N, out + 4 * N,
        ETAf, DTPMf, GPMf);

    // pass n = 1: layer-0 neighbor velocities come from the updated output; center = layer 1
    dem_pass<<<grid, block, shmem>>>(
        x, y, z, out + 0 * N, out + 2 * N, out + 4 * N,
        x + N, y + N, z + N, vx + N, vy + N, vz + N,
        x + N, y + N, z + N, vx + N, vy + N, vz + N,
        mask + N,
        out + 1 * N, out + 3 * N, out + 5 * N,
        ETAf, DTPMf, GPMf);
}

// round 8
// speedup vs baseline: 1.2386x; 1.2386x over previous
#include <cuda_runtime.h>
#include <math.h>

#define DD 128
static const int NC = DD * DD * DD;   // cells per layer

// smem: 2 layers x 6 fields x 36 rows (6z x 6y halo) x 128 floats
#define FROWS 36
#define FSTRIDE (FROWS * 128)          // 4608 floats per (layer,field)
#define SMEM_FLOATS (12 * FSTRIDE)     // 55296 floats = 221184 B

typedef unsigned long long f2;         // packed f32x2

__device__ __forceinline__ f2 pk(float lo, float hi) {
    f2 r; asm("mov.b64 %0,{%1,%2};" : "=l"(r) : "f"(lo), "f"(hi)); return r;
}
__device__ __forceinline__ void up(f2 v, float& lo, float& hi) {
    asm("mov.b64 {%0,%1},%2;" : "=f"(lo), "=f"(hi) : "l"(v));
}
__device__ __forceinline__ f2 fma2(f2 a, f2 b, f2 c) {
    f2 d; asm("fma.rn.f32x2 %0,%1,%2,%3;" : "=l"(d) : "l"(a), "l"(b), "l"(c)); return d;
}
__device__ __forceinline__ f2 mul2(f2 a, f2 b) {
    f2 d; asm("mul.rn.f32x2 %0,%1,%2;" : "=l"(d) : "l"(a), "l"(b)); return d;
}
__device__ __forceinline__ float rsqrt_fast(float x) {
    float y; asm("rsqrt.approx.f32 %0, %1;" : "=f"(y) : "f"(x)); return y;
}

__device__ __forceinline__ float boundary_force(float p, float v, float mv, float ETAf) {
    float lo = (p > 0.1f && p < 0.15f) ? mv : 0.0f;
    float hi = (p > 12.65f) ? mv : 0.0f;
    float fb = 6.0e6f * lo * (0.15f - p);
    fb -= 6.0e6f * hi * (((p - 12.8f) + 0.1f) + 0.05f);
    fb -= ETAf * v * lo;
    fb -= ETAf * v * hi;
    return fb;
}

struct Consts { f2 NEG1, EPS2, KN2, NKPS2, ETA2; };

// One packed interaction: 2 cells (packed centers C[0..5]) vs one window column
// supplied as 12 scalars, packed just-in-time.
__device__ __forceinline__ void interact(
    const f2* __restrict__ C,
    float wxl, float wxh, float wyl, float wyh, float wzl, float wzh,
    float wvxl, float wvxh, float wvyl, float wvyh, float wvzl, float wvzh,
    f2& FX, f2& FY, f2& FZ, const Consts& K)
{
    f2 dx2 = fma2(pk(wxl, wxh), K.NEG1, C[0]);
    f2 dy2 = fma2(pk(wyl, wyh), K.NEG1, C[1]);
    f2 dz2 = fma2(pk(wzl, wzh), K.NEG1, C[2]);
    f2 s2  = fma2(dz2, dz2, K.EPS2);     // +1e-8 floor folded in
    s2 = fma2(dy2, dy2, s2);
    s2 = fma2(dx2, dx2, s2);
    float s0, s1; up(s2, s0, s1);
    float r0 = rsqrt_fast(s0);
    float r1 = rsqrt_fast(s1);
    r0 = (s0 < 0.01f) ? r0 : 0.0f;       // contact gate folded into r
    r1 = (s1 < 0.01f) ? r1 : 0.0f;
    f2 rg = pk(r0, r1);
    f2 dist2 = mul2(s2, rg);             // = sqrt(s2) where gated-in, else 0
    f2 dvx2 = fma2(pk(wvxl, wvxh), K.NEG1, C[3]);
    f2 dvy2 = fma2(pk(wvyl, wvyh), K.NEG1, C[4]);
    f2 dvz2 = fma2(pk(wvzl, wvzh), K.NEG1, C[5]);
    f2 dot2 = mul2(dvz2, dz2);
    dot2 = fma2(dvy2, dy2, dot2);
    dot2 = fma2(dvx2, dx2, dot2);
    f2 q2 = mul2(dot2, rg);              // dvn/dc (dc clamp automatic: r<=1e4)
    f2 t2 = fma2(K.KN2, dist2, K.NKPS2); // KN*(dist-PS)
    t2 = fma2(K.ETA2, q2, t2);
    f2 coef2 = mul2(t2, rg);             // zero where gated-out
    FX = fma2(coef2, dx2, FX);
    FY = fma2(coef2, dy2, FY);
    FZ = fma2(coef2, dz2, FZ);
}

// window value j (0..5) of field f from quad + shuffle edges
#define WIN(f, j) ((j) == 0 ? s0_[f] : (j) == 1 ? q_[f].x : (j) == 2 ? q_[f].y : \
                   (j) == 3 ? q_[f].z : (j) == 4 ? q_[f].w : s5_[f])

__global__ void __launch_bounds__(512, 1)
dem_pass(const float* __restrict__ nx0, const float* __restrict__ ny0, const float* __restrict__ nz0,
         const float* __restrict__ nvx0, const float* __restrict__ nvy0, const float* __restrict__ nvz0,
         const float* __restrict__ nx1, const float* __restrict__ ny1, const float* __restrict__ nz1,
         const float* __restrict__ nvx1, const float* __restrict__ nvy1, const float* __restrict__ nvz1,
         const float* __restrict__ cx, const float* __restrict__ cy, const float* __restrict__ cz,
         const float* __restrict__ cvx, const float* __restrict__ cvy, const float* __restrict__ cvz,
         const float* __restrict__ cmask,
         float* __restrict__ ovx, float* __restrict__ ovy, float* __restrict__ ovz,
         float ETAf, float DTPMf, float GPMf)
{
    extern __shared__ float sm[];

    const int lane = threadIdx.x;                    // 0..31, x-quads
    const int ty = threadIdx.y;                      // 0..3 (y in tile)
    const int tz = threadIdx.z;                      // 0..3 (z in tile)
    const int tid = (tz * 4 + ty) * 32 + lane;       // 0..511
    const int by4 = blockIdx.x * 4;                  // y tile base
    const int bz4 = blockIdx.y * 4;                  // z tile base
    const int base = ((bz4 + tz) * DD + (by4 + ty)) * DD + lane * 4;

    Consts K;
    K.NEG1  = pk(-1.0f, -1.0f);
    K.EPS2  = pk(1e-8f, 1e-8f);
    K.KN2   = pk(6.0e6f, 6.0e6f);
    K.NKPS2 = pk(-600000.0f, -600000.0f);
    K.ETA2  = pk(ETAf, ETAf);

    // center values (layer n) -> packed only
    f2 C0[6], C1[6];
    {
        float4 a;
        a = *reinterpret_cast<const float4*>(cx + base);
        C0[0] = pk(a.x, a.y); C1[0] = pk(a.z, a.w);
        a = *reinterpret_cast<const float4*>(cy + base);
        C0[1] = pk(a.x, a.y); C1[1] = pk(a.z, a.w);
        a = *reinterpret_cast<const float4*>(cz + base);
        C0[2] = pk(a.x, a.y); C1[2] = pk(a.z, a.w);
        a = *reinterpret_cast<const float4*>(cvx + base);
        C0[3] = pk(a.x, a.y); C1[3] = pk(a.z, a.w);
        a = *reinterpret_cast<const float4*>(cvy + base);
        C0[4] = pk(a.x, a.y); C1[4] = pk(a.z, a.w);
        a = *reinterpret_cast<const float4*>(cvz + base);
        C0[5] = pk(a.x, a.y); C1[5] = pk(a.z, a.w);
    }

    // single fill: both layers, 12 (layer,field) slabs x 36 rows x 32 float4s
    {
        const float* NL[12] = {nx0, ny0, nz0, nvx0, nvy0, nvz0,
                               nx1, ny1, nz1, nvx1, nvy1, nvz1};
#pragma unroll
        for (int it = 0; it < 27; ++it) {
            int g = tid + it * 512;                // 0..13823
            int fl = g / 1152, rem = g - fl * 1152;
            int r = rem >> 5, x4 = (rem & 31) * 4;
            int gy = (by4 + (r % 6) - 1) & 127;
            int gz = (bz4 + (r / 6) - 1) & 127;
            *reinterpret_cast<float4*>(sm + fl * FSTRIDE + r * 128 + x4) =
                *reinterpret_cast<const float4*>(NL[fl] + (gz * DD + gy) * DD + x4);
        }
    }
    __syncthreads();

    f2 FX0 = 0, FY0 = 0, FZ0 = 0;     // accumulators for cells (0,1)
    f2 FX1 = 0, FY1 = 0, FZ1 = 0;     // accumulators for cells (2,3)

#pragma unroll
    for (int m = 0; m < 2; ++m) {
        const float* smb = sm + m * 6 * FSTRIDE;
#pragma unroll
        for (int dz = 0; dz < 3; ++dz) {
#pragma unroll
            for (int dy = 0; dy < 3; ++dy) {
                const int roff = ((tz + dz) * 6 + (ty + dy)) * 128 + lane * 4;
                float4 q_[6];
                float s0_[6], s5_[6];
#pragma unroll
                for (int f = 0; f < 6; ++f) {
                    q_[f] = *reinterpret_cast<const float4*>(smb + f * FSTRIDE + roff);
                    // circular warp shuffle = periodic x wrap (warp covers full x axis)
                    s0_[f] = __shfl_sync(0xffffffffu, q_[f].w, (lane + 31) & 31);
                    s5_[f] = __shfl_sync(0xffffffffu, q_[f].x, (lane + 1) & 31);
                }
#pragma unroll
                for (int j = 0; j < 3; ++j) {
                    interact(C0,
                             WIN(0, j), WIN(0, j + 1), WIN(1, j), WIN(1, j + 1),
                             WIN(2, j), WIN(2, j + 1), WIN(3, j), WIN(3, j + 1),
                             WIN(4, j), WIN(4, j + 1), WIN(5, j), WIN(5, j + 1),
                             FX0, FY0, FZ0, K);
                    interact(C1,
                             WIN(0, j + 2), WIN(0, j + 3), WIN(1, j + 2), WIN(1, j + 3),
                             WIN(2, j + 2), WIN(2, j + 3), WIN(3, j + 2), WIN(3, j + 3),
                             WIN(4, j + 2), WIN(4, j + 3), WIN(5, j + 2), WIN(5, j + 3),
                             FX1, FY1, FZ1, K);
                }
            }
        }
    }

    // epilogue: unpack accumulators and centers; reload mask late
    float fxa[4], fya[4], fza[4];
    up(FX0, fxa[0], fxa[1]); up(FX1, fxa[2], fxa[3]);
    up(FY0, fya[0], fya[1]); up(FY1, fya[2], fya[3]);
    up(FZ0, fza[0], fza[1]); up(FZ1, fza[2], fza[3]);

    float xn[4], yn[4], zn[4], vxn[4], vyn[4], vzn[4];
    up(C0[0], xn[0], xn[1]);  up(C1[0], xn[2], xn[3]);
    up(C0[1], yn[0], yn[1]);  up(C1[1], yn[2], yn[3]);
    up(C0[2], zn[0], zn[1]);  up(C1[2], zn[2], zn[3]);
    up(C0[3], vxn[0], vxn[1]); up(C1[3], vxn[2], vxn[3]);
    up(C0[4], vyn[0], vyn[1]); up(C1[4], vyn[2], vyn[3]);
    up(C0[5], vzn[0], vzn[1]); up(C1[5], vzn[2], vzn[3]);

    float4 mk4 = *reinterpret_cast<const float4*>(cmask + base);
    const float mk[4] = {mk4.x, mk4.y, mk4.z, mk4.w};

    float outx[4], outy[4], outz[4];
#pragma unroll
    for (int c = 0; c < 4; ++c) {
        float mv = mk[c];
        float fxb = boundary_force(xn[c], vxn[c], mv, ETAf);
        float fyb = boundary_force(yn[c], vyn[c], mv, ETAf);
        float fzb = boundary_force(zn[c], vzn[c], mv, ETAf);
        float sc = DTPMf * mv;
        outx[c] = vxn[c] + sc * (fxb - fxa[c]);
        outy[c] = vyn[c] + sc * (fyb - fya[c]);
        outz[c] = vzn[c] + sc * ((GPMf - fza[c]) + fzb);
    }
    *reinterpret_cast<float4*>(ovx + base) = make_float4(outx[0], outx[1], outx[2], outx[3]);
    *reinterpret_cast<float4*>(ovy + base) = make_float4(outy[0], outy[1], outy[2], outy[3]);
    *reinterpret_cast<float4*>(ovz + base) = make_float4(outz[0], outz[1], outz[2], outz[3]);
}

extern "C" void kernel_launch(void* const* d_in, const int* in_sizes, int n_in,
                              void* d_out, int out_size)
{
    const float* x  = (const float*)d_in[0];
    const float* y  = (const float*)d_in[1];
    const float* z  = (const float*)d_in[2];
    const float* vx = (const float*)d_in[3];
    const float* vy = (const float*)d_in[4];
    const float* vz = (const float*)d_in[5];
    const float* mask = (const float*)d_in[6];
    float* out = (float*)d_out;
    const int N = NC;

    const double PI = 3.141592653589793;
    const double ALPHA = 0.6931471805599453 / PI;          // -log(0.5)/pi
    const double GAMMA = ALPHA / sqrt(ALPHA * ALPHA + 1.0);
    const double PM = 4.0 / 3.0 * 3.1415 * (0.1 * 0.1 * 0.1) * 2700.0;
    const double ETA = 2.0 * GAMMA * sqrt(6.0e6 * PM);
    const float ETAf  = (float)ETA;
    const float DTPMf = (float)(1e-4 / PM);
    const float GPMf  = (float)(-9.8 * PM);

    cudaFuncSetAttribute(dem_pass, cudaFuncAttributeMaxDynamicSharedMemorySize,
                         SMEM_FLOATS * (int)sizeof(float));

    dim3 grid(32, 32);        // 128/4 y-tiles, 128/4 z-tiles
    dim3 block(32, 4, 4);     // 512 threads, 4 x-cells each
    size_t shmem = SMEM_FLOATS * sizeof(float);

    // pass n = 0: neighbors use original velocities of both layers; center = layer 0
    dem_pass<<<grid, block, shmem>>>(
        x, y, z, vx, vy, vz,
        x + N, y + N, z + N, vx + N, vy + N, vz + N,
        x, y, z, vx, vy, vz,
        mask,
        out + 0 * N, out + 2 * N, out + 4 * N,
        ETAf, DTPMf, GPMf);

    // pass n = 1: layer-0 neighbor velocities come from the updated output; center = layer 1
    dem_pass<<<grid, block, shmem>>>(
        x, y, z, out + 0 * N, out + 2 * N, out + 4 * N,
        x + N, y + N, z + N, vx + N, vy + N, vz + N,
        x + N, y + N, z + N, vx + N, vy + N, vz + N,
        mask + N,
        out + 1 * N, out + 3 * N, out + 5 * N,
        ETAf, DTPMf, GPMf);
}

// round 9
// speedup vs baseline: 1.8843x; 1.5212x over previous
#include <cuda_runtime.h>
#include <math.h>

#define DD 128
static const int NC = DD * DD * DD;   // cells per layer

// smem: 6 fields x (TZ+2)=4 z x (TY+2)=6 y x 128 floats
#define F_STRIDE (4 * 6 * 128)        // 3072 floats per field
#define SMEM_FLOATS (6 * F_STRIDE)    // 18432 floats = 73728 B

typedef unsigned long long f2;        // packed f32x2

__device__ __forceinline__ f2 pk(float lo, float hi) {
    f2 r; asm("mov.b64 %0,{%1,%2};" : "=l"(r) : "f"(lo), "f"(hi)); return r;
}
__device__ __forceinline__ void up(f2 v, float& lo, float& hi) {
    asm("mov.b64 {%0,%1},%2;" : "=f"(lo), "=f"(hi) : "l"(v));
}
__device__ __forceinline__ f2 fma2(f2 a, f2 b, f2 c) {
    f2 d; asm("fma.rn.f32x2 %0,%1,%2,%3;" : "=l"(d) : "l"(a), "l"(b), "l"(c)); return d;
}
__device__ __forceinline__ f2 mul2(f2 a, f2 b) {
    f2 d; asm("mul.rn.f32x2 %0,%1,%2;" : "=l"(d) : "l"(a), "l"(b)); return d;
}
__device__ __forceinline__ float rsqrt_fast(float x) {
    float y; asm("rsqrt.approx.f32 %0, %1;" : "=f"(y) : "f"(x)); return y;
}

__device__ __forceinline__ float boundary_force(float p, float v, float mv, float ETAf) {
    float lo = (p > 0.1f && p < 0.15f) ? mv : 0.0f;
    float hi = (p > 12.65f) ? mv : 0.0f;
    float fb = 6.0e6f * lo * (0.15f - p);
    fb -= 6.0e6f * hi * (((p - 12.8f) + 0.1f) + 0.05f);
    fb -= ETAf * v * lo;
    fb -= ETAf * v * hi;
    return fb;
}

struct Consts { f2 NEG1, EPS2, KN2, NKPS2, ETA2; };

// One packed interaction: 2 cells (packed centers C[0..5]) vs one window column.
__device__ __forceinline__ void interact(
    const f2* __restrict__ C,
    float wxl, float wxh, float wyl, float wyh, float wzl, float wzh,
    float wvxl, float wvxh, float wvyl, float wvyh, float wvzl, float wvzh,
    f2& FX, f2& FY, f2& FZ, const Consts& K)
{
    f2 dx2 = fma2(pk(wxl, wxh), K.NEG1, C[0]);
    f2 dy2 = fma2(pk(wyl, wyh), K.NEG1, C[1]);
    f2 dz2 = fma2(pk(wzl, wzh), K.NEG1, C[2]);
    f2 s2  = fma2(dz2, dz2, K.EPS2);     // +1e-8 floor folded in
    s2 = fma2(dy2, dy2, s2);
    s2 = fma2(dx2, dx2, s2);
    float s0, s1; up(s2, s0, s1);
    float r0 = rsqrt_fast(s0);
    float r1 = rsqrt_fast(s1);
    r0 = (s0 < 0.01f) ? r0 : 0.0f;       // contact gate folded into r
    r1 = (s1 < 0.01f) ? r1 : 0.0f;
    f2 rg = pk(r0, r1);
    f2 dist2 = mul2(s2, rg);             // = sqrt(s2) where gated-in, else 0
    f2 dvx2 = fma2(pk(wvxl, wvxh), K.NEG1, C[3]);
    f2 dvy2 = fma2(pk(wvyl, wvyh), K.NEG1, C[4]);
    f2 dvz2 = fma2(pk(wvzl, wvzh), K.NEG1, C[5]);
    f2 dot2 = mul2(dvz2, dz2);
    dot2 = fma2(dvy2, dy2, dot2);
    dot2 = fma2(dvx2, dx2, dot2);
    f2 q2 = mul2(dot2, rg);              // dvn/dc (dc clamp automatic: r<=1e4)
    f2 t2 = fma2(K.KN2, dist2, K.NKPS2); // KN*(dist-PS)
    t2 = fma2(K.ETA2, q2, t2);
    f2 coef2 = mul2(t2, rg);             // zero where gated-out
    FX = fma2(coef2, dx2, FX);
    FY = fma2(coef2, dy2, FY);
    FZ = fma2(coef2, dz2, FZ);
}

// window value j (0..5) of field f from quad + shuffle edges
#define WIN(f, j) ((j) == 0 ? s0_[f] : (j) == 1 ? q_[f].x : (j) == 2 ? q_[f].y : \
                   (j) == 3 ? q_[f].z : (j) == 4 ? q_[f].w : s5_[f])

__global__ void __launch_bounds__(256, 2)
dem_pass(const float* __restrict__ x0, const float* __restrict__ y0, const float* __restrict__ z0,
         const float* __restrict__ x1, const float* __restrict__ y1, const float* __restrict__ z1,
         const float* __restrict__ vxl0, const float* __restrict__ vyl0, const float* __restrict__ vzl0,
         const float* __restrict__ vxl1, const float* __restrict__ vyl1, const float* __restrict__ vzl1,
         const float* __restrict__ cx, const float* __restrict__ cy, const float* __restrict__ cz,
         const float* __restrict__ cvx, const float* __restrict__ cvy, const float* __restrict__ cvz,
         const float* __restrict__ cmask,
         float* __restrict__ ovx, float* __restrict__ ovy, float* __restrict__ ovz,
         float ETAf, float DTPMf, float GPMf)
{
    extern __shared__ float sm[];

    const int lane = threadIdx.x;                    // 0..31, x-quads
    const int ty = threadIdx.y;                      // 0..3
    const int tz = threadIdx.z;                      // 0..1
    const int tid = (tz * 4 + ty) * 32 + lane;       // 0..255
    const int by0 = blockIdx.x * 4;                  // y tile base
    const int bz0 = blockIdx.y * 2;                  // z tile base
    const int yc = by0 + ty;
    const int zc = bz0 + tz;
    const int base = (zc * DD + yc) * DD + lane * 4; // center cell (first of quad)

    Consts K;
    K.NEG1  = pk(-1.0f, -1.0f);
    K.EPS2  = pk(1e-8f, 1e-8f);
    K.KN2   = pk(6.0e6f, 6.0e6f);
    K.NKPS2 = pk(-600000.0f, -600000.0f);
    K.ETA2  = pk(ETAf, ETAf);

    // center values (layer n) -> packed only
    f2 C0[6], C1[6];
    {
        float4 a;
        a = *reinterpret_cast<const float4*>(cx + base);
        C0[0] = pk(a.x, a.y); C1[0] = pk(a.z, a.w);
        a = *reinterpret_cast<const float4*>(cy + base);
        C0[1] = pk(a.x, a.y); C1[1] = pk(a.z, a.w);
        a = *reinterpret_cast<const float4*>(cz + base);
        C0[2] = pk(a.x, a.y); C1[2] = pk(a.z, a.w);
        a = *reinterpret_cast<const float4*>(cvx + base);
        C0[3] = pk(a.x, a.y); C1[3] = pk(a.z, a.w);
        a = *reinterpret_cast<const float4*>(cvy + base);
        C0[4] = pk(a.x, a.y); C1[4] = pk(a.z, a.w);
        a = *reinterpret_cast<const float4*>(cvz + base);
        C0[5] = pk(a.x, a.y); C1[5] = pk(a.z, a.w);
    }

    f2 FX0 = 0, FY0 = 0, FZ0 = 0;     // accumulators for cells (0,1)
    f2 FX1 = 0, FY1 = 0, FZ1 = 0;     // accumulators for cells (2,3)

    const int colo = lane * 4;

#pragma unroll
    for (int m = 0; m < 2; ++m) {
        const float* Ps[6];
        Ps[0] = m ? x1 : x0;   Ps[1] = m ? y1 : y0;   Ps[2] = m ? z1 : z0;
        Ps[3] = m ? vxl1 : vxl0; Ps[4] = m ? vyl1 : vyl0; Ps[5] = m ? vzl1 : vzl0;

        if (m) __syncthreads();   // protect previous phase's reads before overwrite

        // cooperative tile load: 24 rows (4z x 6y) of 128 floats per field
#pragma unroll
        for (int f = 0; f < 6; ++f) {
            const float* p = Ps[f];
            float* s = sm + f * F_STRIDE;
#pragma unroll
            for (int it = 0; it < 3; ++it) {
                int t = tid + it * 256;            // 0..767 (float4 granules)
                int row = t >> 5;
                int l = t & 31;
                int lz = row / 6;
                int ly = row - lz * 6;
                int gz = (bz0 + lz - 1) & 127;
                int gy = (by0 + ly - 1) & 127;
                *reinterpret_cast<float4*>(s + row * 128 + l * 4) =
                    *reinterpret_cast<const float4*>(p + (gz * DD + gy) * DD + l * 4);
            }
        }
        __syncthreads();

        // 9 rows (3z x 3y), software-pipelined: prefetch row r+1 quads before
        // doing row r's shuffles + interacts.
        float4 q_[6];
        {
            const int roff0 = (tz * 6 + ty) * 128 + colo;      // r=0 -> (dz=0,dy=0)
#pragma unroll
            for (int f = 0; f < 6; ++f)
                q_[f] = *reinterpret_cast<const float4*>(sm + f * F_STRIDE + roff0);
        }
#pragma unroll
        for (int r = 0; r < 9; ++r) {
            float4 qn[6];
            if (r < 8) {
                const int rn = r + 1;
                const int roffn = ((tz + rn / 3) * 6 + (ty + rn % 3)) * 128 + colo;
#pragma unroll
                for (int f = 0; f < 6; ++f)
                    qn[f] = *reinterpret_cast<const float4*>(sm + f * F_STRIDE + roffn);
            }
            float s0_[6], s5_[6];
#pragma unroll
            for (int f = 0; f < 6; ++f) {
                // circular warp shuffle = periodic x wrap (warp covers full x axis)
                s0_[f] = __shfl_sync(0xffffffffu, q_[f].w, (lane + 31) & 31);
                s5_[f] = __shfl_sync(0xffffffffu, q_[f].x, (lane + 1) & 31);
            }
#pragma unroll
            for (int j = 0; j < 3; ++j) {
                interact(C0,
                         WIN(0, j), WIN(0, j + 1), WIN(1, j), WIN(1, j + 1),
                         WIN(2, j), WIN(2, j + 1), WIN(3, j), WIN(3, j + 1),
                         WIN(4, j), WIN(4, j + 1), WIN(5, j), WIN(5, j + 1),
                         FX0, FY0, FZ0, K);
                interact(C1,
                         WIN(0, j + 2), WIN(0, j + 3), WIN(1, j + 2), WIN(1, j + 3),
                         WIN(2, j + 2), WIN(2, j + 3), WIN(3, j + 2), WIN(3, j + 3),
                         WIN(4, j + 2), WIN(4, j + 3), WIN(5, j + 2), WIN(5, j + 3),
                         FX1, FY1, FZ1, K);
            }
            if (r < 8) {
#pragma unroll
                for (int f = 0; f < 6; ++f) q_[f] = qn[f];   // renamed away by unroll
            }
        }
    }

    // epilogue: unpack accumulators and centers; load mask late
    float fxa[4], fya[4], fza[4];
    up(FX0, fxa[0], fxa[1]); up(FX1, fxa[2], fxa[3]);
    up(FY0, fya[0], fya[1]); up(FY1, fya[2], fya[3]);
    up(FZ0, fza[0], fza[1]); up(FZ1, fza[2], fza[3]);

    float xn[4], yn[4], zn[4], vxn[4], vyn[4], vzn[4];
    up(C0[0], xn[0], xn[1]);  up(C1[0], xn[2], xn[3]);
    up(C0[1], yn[0], yn[1]);  up(C1[1], yn[2], yn[3]);
    up(C0[2], zn[0], zn[1]);  up(C1[2], zn[2], zn[3]);
    up(C0[3], vxn[0], vxn[1]); up(C1[3], vxn[2], vxn[3]);
    up(C0[4], vyn[0], vyn[1]); up(C1[4], vyn[2], vyn[3]);
    up(C0[5], vzn[0], vzn[1]); up(C1[5], vzn[2], vzn[3]);

    float4 mk4 = *reinterpret_cast<const float4*>(cmask + base);
    const float mk[4] = {mk4.x, mk4.y, mk4.z, mk4.w};

    float outx[4], outy[4], outz[4];
#pragma unroll
    for (int c = 0; c < 4; ++c) {
        float mv = mk[c];
        float fxb = boundary_force(xn[c], vxn[c], mv, ETAf);
        float fyb = boundary_force(yn[c], vyn[c], mv, ETAf);
        float fzb = boundary_force(zn[c], vzn[c], mv, ETAf);
        float sc = DTPMf * mv;
        outx[c] = vxn[c] + sc * (fxb - fxa[c]);
        outy[c] = vyn[c] + sc * (fyb - fya[c]);
        outz[c] = vzn[c] + sc * ((GPMf - fza[c]) + fzb);
    }
    *reinterpret_cast<float4*>(ovx + base) = make_float4(outx[0], outx[1], outx[2], outx[3]);
    *reinterpret_cast<float4*>(ovy + base) = make_float4(outy[0], outy[1], outy[2], outy[3]);
    *reinterpret_cast<float4*>(ovz + base) = make_float4(outz[0], outz[1], outz[2], outz[3]);
}

extern "C" void kernel_launch(void* const* d_in, const int* in_sizes, int n_in,
                              void* d_out, int out_size)
{
    const float* x  = (const float*)d_in[0];
    const float* y  = (const float*)d_in[1];
    const float* z  = (const float*)d_in[2];
    const float* vx = (const float*)d_in[3];
    const float* vy = (const float*)d_in[4];
    const float* vz = (const float*)d_in[5];
    const float* mask = (const float*)d_in[6];
    float* out = (float*)d_out;
    const int N = NC;

    const double PI = 3.141592653589793;
    const double ALPHA = 0.6931471805599453 / PI;          // -log(0.5)/pi
    const double GAMMA = ALPHA / sqrt(ALPHA * ALPHA + 1.0);
    const double PM = 4.0 / 3.0 * 3.1415 * (0.1 * 0.1 * 0.1) * 2700.0;
    const double ETA = 2.0 * GAMMA * sqrt(6.0e6 * PM);
    const float ETAf  = (float)ETA;
    const float DTPMf = (float)(1e-4 / PM);
    const float GPMf  = (float)(-9.8 * PM);

    cudaFuncSetAttribute(dem_pass, cudaFuncAttributeMaxDynamicSharedMemorySize,
                         SMEM_FLOATS * (int)sizeof(float));

    dim3 grid(32, 64);      // 128/4 y-tiles, 128/2 z-tiles
    dim3 block(32, 4, 2);
    size_t shmem = SMEM_FLOATS * sizeof(float);

    // pass n = 0: neighbors use original velocities of both layers
    dem_pass<<<grid, block, shmem>>>(
        x, y, z, x + N, y + N, z + N,
        vx, vy, vz, vx + N, vy + N, vz + N,
        x, y, z, vx, vy, vz,
        mask,
        out + 0 * N, out + 2 * N, out + 4 * N,
        ETAf, DTPMf, GPMf);

    // pass n = 1: layer-0 neighbor velocities come from updated output
    dem_pass<<<grid, block, shmem>>>(
        x, y, z, x + N, y + N, z + N,
        out + 0 * N, out + 2 * N, out + 4 * N,
        vx + N, vy + N, vz + N,
        x + N, y + N, z + N, vx + N, vy + N, vz + N,
        mask + N,
        out + 1 * N, out + 3 * N, out + 5 * N,
        ETAf, DTPMf, GPMf);
}